// round 3
// baseline (speedup 1.0000x reference)
#include <cuda_runtime.h>
#include <math.h>

// ConvCaps EM routing (b=8, B=C=32, K=3, s=2, Win=13, Wout=6, 3 EM iters).
// Votes are never materialized: recomputed from smem pose patch x L2-resident W.
// One block per (n,x,y); lane = output capsule c; per-warp register moments;
// kperm self-inverse trick folds the E-step into the vote recompute sweep.

#define RP0 (1.0f / 1152.0f)
#define LOG2PI 1.8378770664093453f

// device-global scratch (no allocations allowed)
__device__ float g_Wt[147456];    // W transposed: [o][ij][p][c][q]
__device__ float g_Rp[2654208];   // p_hat: [n][o][ij][xy][c]
__device__ float g_D0[43264];     // D normalizer ping: [n][o][13][13]
__device__ float g_D1[43264];     // pong

// -------- prep: transpose W for coalesced lane reads; zero D buffers --------
// dst layout [o][ij][p][c][q]: idx = ((o*9+ij)*4+p)*128 + c*4 + q
__global__ void prep_kernel(const float* __restrict__ W) {
    int idx = blockIdx.x * 256 + threadIdx.x;
    if (idx < 147456) {
        int q   = idx & 3;
        int c   = (idx >> 2) & 31;
        int p   = (idx >> 7) & 3;
        int oij = idx >> 9;           // = o*9 + ij  (o outermost)
        int o   = oij / 9;
        int ij  = oij - o * 9;
        // src: W[i,j,o,c,p,q] = (((ij*32+o)*32+c)*4+p)*4+q
        g_Wt[idx] = W[(((ij * 32 + o) * 32 + c) * 4 + p) * 4 + q];
    }
    if (idx < 43264) { g_D0[idx] = 0.0f; g_D1[idx] = 0.0f; }
}

// smem: pose 4608 | a 288 | red 8448 | mom 1056 | mu 544 | sfac 32 = 14976 f
#define SMEM_FLOATS 14976

template <int ITER>
__global__ void __launch_bounds__(256, 2) iter_kernel(
    const float* __restrict__ x,
    const float* __restrict__ bv_p,
    const float* __restrict__ ba_p,
    const float* __restrict__ lam_p,
    float* __restrict__ out)
{
    extern __shared__ float sm[];
    float* pose_s = sm;            // [o][ij][qr] : 32*9*16
    float* a_s    = sm + 4608;     // [o*9+ij]
    float* red    = sm + 4896;     // [w][c][33]
    float* mom    = sm + 13344;    // [c][33]
    float* mu_s   = sm + 14400;    // [c][17] (stride 17: conflict-free)
    float* sfac_s = sm + 14944;    // [c]

    const int xy = blockIdx.x;     // 0..35
    const int n  = blockIdx.y;     // 0..7
    const int X = xy / 6, Y = xy % 6;
    const int tid = threadIdx.x;
    const int w = tid >> 5;        // warp 0..7
    const int c = tid & 31;        // lane = output capsule

    const float* xn = x + n * (544 * 169);
    const int base = (2 * X) * 13 + 2 * Y;

    // ---- load pose + act patch into smem ----
    for (int e = tid; e < 512; e += 256) {          // channel e = qr*32 + o
        int o = e & 31, qr = e >> 5;
        const float* src = xn + e * 169 + base;
        float* dst = pose_s + o * 144 + qr;
        #pragma unroll
        for (int i = 0; i < 3; i++)
            #pragma unroll
            for (int j = 0; j < 3; j++)
                dst[(i * 3 + j) * 16] = src[i * 13 + j];
    }
    for (int e = tid; e < 288; e += 256) {
        int o = e / 9, ij = e - o * 9;
        int i = ij / 3, j = ij - i * 3;
        a_s[e] = xn[(512 + o) * 169 + base + i * 13 + j];
    }
    __syncthreads();

    // ---- M phase: register moments over this warp's 36 (o,i,j) ----
    float m1[16], m2[16];
    #pragma unroll
    for (int d = 0; d < 16; d++) { m1[d] = 0.0f; m2[d] = 0.0f; }
    float sumr = 0.0f;

    const float* Din = (ITER == 1) ? g_D0 : g_D1;

    #pragma unroll 1
    for (int oo = 0; oo < 4; oo++) {
        int o = w * 4 + oo;
        #pragma unroll 3
        for (int ij = 0; ij < 9; ij++) {
            int i2 = ij / 3, j2 = ij - i2 * 3;
            int oij = o * 9 + ij;
            float a = a_s[oij];
            float rh;
            if (ITER == 0) {
                rh = a * RP0;
            } else {
                float ph = g_Rp[(((n * 32 + o) * 9 + ij) * 36 + xy) * 32 + c];
                float Dv = Din[((n * 32 + o) * 13 + 2 * X + i2) * 13 + 2 * Y + j2];
                rh = ph / Dv * a;
            }
            sumr += rh;
            const float* pp = pose_s + oij * 16;
            float P[16];
            #pragma unroll
            for (int k = 0; k < 4; k++) {
                float4 t4 = *(const float4*)(pp + 4 * k);   // broadcast LDS
                P[4*k+0] = t4.x; P[4*k+1] = t4.y; P[4*k+2] = t4.z; P[4*k+3] = t4.w;
            }
            const float4* wp = (const float4*)g_Wt + oij * 128 + c;   // [o][ij] layout
            #pragma unroll
            for (int p = 0; p < 4; p++) {
                float4 wv = wp[p * 32];                     // coalesced LDG.128
                #pragma unroll
                for (int r = 0; r < 4; r++) {
                    float v = fmaf(wv.x, P[r],
                              fmaf(wv.y, P[4 + r],
                              fmaf(wv.z, P[8 + r], wv.w * P[12 + r])));
                    int d = p * 4 + r;
                    float t = rh * v;
                    m1[d] += t;
                    m2[d] = fmaf(t, v, m2[d]);
                }
            }
        }
    }

    // ---- block reduction: 33 values per c over 8 warps ----
    {
        float* myred = red + (w * 32 + c) * 33;
        #pragma unroll
        for (int d = 0; d < 16; d++) { myred[d] = m1[d]; myred[16 + d] = m2[d]; }
        myred[32] = sumr;
    }
    __syncthreads();
    for (int s = tid; s < 1056; s += 256) {
        float acc = 0.0f;
        #pragma unroll
        for (int ww = 0; ww < 8; ww++) acc += red[ww * 1056 + s];
        mom[s] = acc;
    }
    __syncthreads();

    // ---- stats per c: mu, sigma, act_out, gaussian prefactor ----
    if (tid < 32) {
        const float* mm = mom + tid * 33;
        float R = mm[32];
        float invR = 1.0f / R;
        float bv = bv_p[0], ba = ba_p[0], lam = lam_p[0];
        float cs = 0.0f;
        #pragma unroll
        for (int d = 0; d < 16; d++) {
            float m  = mm[d] * invR;
            float sg = fmaf(-m, m, mm[16 + d] * invR);   // E[rv^2]/R - mu^2
            mu_s[tid * 17 + d] = m;
            cs += logf(sg);
        }
        float cost = R * fmaf(16.0f, bv, cs);            // sum_d (bv+log s)*R
        float act  = 1.0f / (1.0f + expf(lam * (cost - ba)));
        if (ITER == 2) {
            float* on = out + (long)n * 19584 + xy;      // out[n][ch][X][Y]
            #pragma unroll
            for (int d = 0; d < 16; d++)
                on[(tid * 16 + d) * 36] = mu_s[tid * 17 + d];
            on[(512 + tid) * 36] = act;
        } else {
            // act * prod_d 1/sqrt(2*pi*sigma_d)
            sfac_s[tid] = act * expf(-0.5f * fmaf(16.0f, LOG2PI, cs));
        }
    }
    __syncthreads();

    // ---- E phase: recompute votes; write p_hat to permuted Rp slot + D ----
    if (ITER < 2) {
        float mu[16];
        #pragma unroll
        for (int d = 0; d < 16; d++) mu[d] = mu_s[c * 17 + d];
        float sf = sfac_s[c];
        float* Dout = (ITER == 0) ? g_D0 : g_D1;

        #pragma unroll 1
        for (int oo = 0; oo < 4; oo++) {
            int o = w * 4 + oo;
            #pragma unroll 3
            for (int ij = 0; ij < 9; ij++) {
                int i2 = ij / 3, j2 = ij - i2 * 3;
                int oij = o * 9 + ij;
                const float* pp = pose_s + oij * 16;
                float P[16];
                #pragma unroll
                for (int k = 0; k < 4; k++) {
                    float4 t4 = *(const float4*)(pp + 4 * k);
                    P[4*k+0] = t4.x; P[4*k+1] = t4.y; P[4*k+2] = t4.z; P[4*k+3] = t4.w;
                }
                const float4* wp = (const float4*)g_Wt + oij * 128 + c;
                float ssd = 0.0f;
                #pragma unroll
                for (int p = 0; p < 4; p++) {
                    float4 wv = wp[p * 32];
                    #pragma unroll
                    for (int r = 0; r < 4; r++) {
                        float v = fmaf(wv.x, P[r],
                                  fmaf(wv.y, P[4 + r],
                                  fmaf(wv.z, P[8 + r], wv.w * P[12 + r])));
                        float dd = v - mu[p * 4 + r];
                        ssd = fmaf(dd, dd, ssd);
                    }
                }
                float ph = sf * __expf(-ssd);
                // warp-sum over c -> T
                float T = ph;
                #pragma unroll
                for (int s = 16; s > 0; s >>= 1)
                    T += __shfl_xor_sync(0xffffffffu, T, s);
                // kperm = [0,2,1] self-inverse: these votes ARE votesE of the
                // permuted slot -> file p_hat there.
                int ip = (3 - i2) % 3;
                int jp = (3 - j2) % 3;
                if (c == 0)
                    atomicAdd(&Dout[((n * 32 + o) * 13 + 2 * X + ip) * 13 + 2 * Y + jp], T);
                g_Rp[(((n * 32 + o) * 9 + ip * 3 + jp) * 36 + xy) * 32 + c] = ph;
            }
        }
    }
}

extern "C" void kernel_launch(void* const* d_in, const int* in_sizes, int n_in,
                              void* d_out, int out_size) {
    const float* x    = (const float*)d_in[0];
    const float* W    = (const float*)d_in[1];
    const float* bv   = (const float*)d_in[2];
    const float* ba   = (const float*)d_in[3];
    const float* lam  = (const float*)d_in[4];
    float* out = (float*)d_out;

    const int smem = SMEM_FLOATS * 4;   // 59904 B
    cudaFuncSetAttribute(iter_kernel<0>, cudaFuncAttributeMaxDynamicSharedMemorySize, smem);
    cudaFuncSetAttribute(iter_kernel<1>, cudaFuncAttributeMaxDynamicSharedMemorySize, smem);
    cudaFuncSetAttribute(iter_kernel<2>, cudaFuncAttributeMaxDynamicSharedMemorySize, smem);

    dim3 grid(36, 8);
    prep_kernel<<<576, 256>>>(W);
    iter_kernel<0><<<grid, 256, smem>>>(x, bv, ba, lam, out);
    iter_kernel<1><<<grid, 256, smem>>>(x, bv, ba, lam, out);
    iter_kernel<2><<<grid, 256, smem>>>(x, bv, ba, lam, out);
}

// round 4
// speedup vs baseline: 1.2540x; 1.2540x over previous
#include <cuda_runtime.h>
#include <math.h>

// ConvCaps EM routing (b=8, B=C=32, K=3, s=2, Win=13, Wout=6, 3 EM iters).
// Fused persistent kernel: all 3 EM iterations in one launch, custom grid
// barrier for the cross-block D normalizer. p_hat kept in smem (block-local).
// Vote math in packed fma.rn.f32x2 (pairs over p; pose duplicated in smem so
// broadcast pairs come straight from LDS.64; W pairs natural via LDG.128).

#define RP0 (1.0f / 1152.0f)
#define LOG2PI 1.8378770664093453f

__device__ float g_Wt[147456];   // [o][ij][q][c][p]
__device__ float g_D0[43264];    // [n][o][13][13]
__device__ float g_D1[43264];
__device__ unsigned g_bar[2];

// -------- prep: W relayout, zero D + barrier counters --------
__global__ void prep_kernel(const float* __restrict__ W) {
    int idx = blockIdx.x * 256 + threadIdx.x;
    if (idx < 147456) {
        int p = idx & 3, c = (idx >> 2) & 31, q = (idx >> 7) & 3;
        int oij = idx >> 9;
        int o = oij / 9, ij = oij - o * 9;
        // src: W[i,j,o,c,p,q]
        g_Wt[idx] = W[(((ij * 32 + o) * 32 + c) * 4 + p) * 4 + q];
    }
    if (idx < 43264) { g_D0[idx] = 0.0f; g_D1[idx] = 0.0f; }
    if (idx < 2) g_bar[idx] = 0u;
}

// -------- packed f32x2 helpers --------
__device__ __forceinline__ unsigned long long f2fma(unsigned long long a, unsigned long long b, unsigned long long c) {
    unsigned long long d; asm("fma.rn.f32x2 %0, %1, %2, %3;" : "=l"(d) : "l"(a), "l"(b), "l"(c)); return d;
}
__device__ __forceinline__ unsigned long long f2mul(unsigned long long a, unsigned long long b) {
    unsigned long long d; asm("mul.rn.f32x2 %0, %1, %2;" : "=l"(d) : "l"(a), "l"(b)); return d;
}
__device__ __forceinline__ unsigned long long f2add(unsigned long long a, unsigned long long b) {
    unsigned long long d; asm("add.rn.f32x2 %0, %1, %2;" : "=l"(d) : "l"(a), "l"(b)); return d;
}
__device__ __forceinline__ unsigned long long f2pack(float lo, float hi) {
    unsigned long long d; asm("mov.b64 %0, {%1, %2};" : "=l"(d) : "f"(lo), "f"(hi)); return d;
}
__device__ __forceinline__ void f2unpack(float& lo, float& hi, unsigned long long v) {
    asm("mov.b64 {%0, %1}, %2;" : "=f"(lo), "=f"(hi) : "l"(v));
}

// smem float offsets
#define SM_POSE2 0        // [oij][qr][2] duplicated pose: 9216
#define SM_A     9216     // 288
#define SM_AD    9504     // 288
#define SM_PH    9792     // [oij][33] p_hat (aliased with red): 9504
#define SM_MOM   19296    // [c][33]: 1056
#define SM_MU    20352    // [c][17]: 544
#define SM_SFAC  20896    // 32
#define SMEM_FLOATS 20928

__global__ void __launch_bounds__(256, 2) fused_kernel(
    const float* __restrict__ x,
    const float* __restrict__ bv_p,
    const float* __restrict__ ba_p,
    const float* __restrict__ lam_p,
    float* __restrict__ out)
{
    extern __shared__ float sm[];
    float* pose2  = sm + SM_POSE2;
    float* a_s    = sm + SM_A;
    float* aD_s   = sm + SM_AD;
    float* ph_s   = sm + SM_PH;
    float* red    = ph_s;          // aliased: red live only between M and stats
    float* mom    = sm + SM_MOM;
    float* mu_s   = sm + SM_MU;
    float* sfac_s = sm + SM_SFAC;

    const int xy = blockIdx.x;     // 0..35
    const int n  = blockIdx.y;     // 0..7
    const int X = xy / 6, Y = xy % 6;
    const int tid = threadIdx.x;
    const int w = tid >> 5;
    const int c = tid & 31;

    const float* xn = x + n * (544 * 169);
    const int base = (2 * X) * 13 + 2 * Y;

    // ---- load patch: duplicated pose (qr-inner for bank spread), act ----
    for (int e = tid; e < 512; e += 256) {
        int qr = e & 15, o = e >> 4;
        const float* src = xn + (qr * 32 + o) * 169 + base;
        #pragma unroll
        for (int i = 0; i < 3; i++)
            #pragma unroll
            for (int j = 0; j < 3; j++) {
                float v = src[i * 13 + j];
                int off = (o * 9 + i * 3 + j) * 32 + qr * 2;
                pose2[off] = v; pose2[off + 1] = v;
            }
    }
    for (int e = tid; e < 288; e += 256) {
        int o = e / 9, ij = e - o * 9;
        float av = xn[(512 + o) * 169 + base + (ij / 3) * 13 + (ij % 3)];
        a_s[e] = av;
        aD_s[e] = av * RP0;        // so iter0: rh = ph(=1) * aD
    }
    for (int e = tid; e < 9504; e += 256) ph_s[e] = 1.0f;
    __syncthreads();

    const float bv = bv_p[0], ba = ba_p[0], lam = lam_p[0];

    for (int it = 0; it < 3; it++) {
        // ================= M phase =================
        unsigned long long m1a[4], m1b[4], m2a[4], m2b[4];
        #pragma unroll
        for (int r = 0; r < 4; r++) { m1a[r]=0ull; m1b[r]=0ull; m2a[r]=0ull; m2b[r]=0ull; }
        float sumr = 0.0f;

        #pragma unroll 1
        for (int oo = 0; oo < 4; oo++) {
            int o = w * 4 + oo;
            #pragma unroll 3
            for (int ij = 0; ij < 9; ij++) {
                int oij = o * 9 + ij;
                float rh = ph_s[oij * 33 + c] * aD_s[oij];
                sumr += rh;
                unsigned long long rh2 = f2pack(rh, rh);
                const unsigned long long* pb = (const unsigned long long*)(pose2 + oij * 32);
                const ulonglong2* wp = (const ulonglong2*)g_Wt + (oij * 4) * 32 + c;
                unsigned long long v0[4], v1[4];
                {
                    ulonglong2 wv = wp[0];
                    #pragma unroll
                    for (int r = 0; r < 4; r++) {
                        unsigned long long P = pb[r];
                        v0[r] = f2mul(wv.x, P); v1[r] = f2mul(wv.y, P);
                    }
                }
                #pragma unroll
                for (int q = 1; q < 4; q++) {
                    ulonglong2 wv = wp[q * 32];
                    #pragma unroll
                    for (int r = 0; r < 4; r++) {
                        unsigned long long P = pb[q * 4 + r];
                        v0[r] = f2fma(wv.x, P, v0[r]); v1[r] = f2fma(wv.y, P, v1[r]);
                    }
                }
                #pragma unroll
                for (int r = 0; r < 4; r++) {
                    unsigned long long t0 = f2mul(rh2, v0[r]);
                    m1a[r] = f2add(m1a[r], t0);
                    m2a[r] = f2fma(t0, v0[r], m2a[r]);
                    unsigned long long t1 = f2mul(rh2, v1[r]);
                    m1b[r] = f2add(m1b[r], t1);
                    m2b[r] = f2fma(t1, v1[r], m2b[r]);
                }
            }
        }
        __syncthreads();   // all ph reads done before red overwrites it

        // pair layout: v0[r] = (d=r, d=4+r), v1[r] = (d=8+r, d=12+r)
        {
            float* myred = red + (w * 32 + c) * 33;
            #pragma unroll
            for (int r = 0; r < 4; r++) {
                float lo, hi;
                f2unpack(lo, hi, m1a[r]); myred[r]      = lo; myred[4 + r]  = hi;
                f2unpack(lo, hi, m1b[r]); myred[8 + r]  = lo; myred[12 + r] = hi;
                f2unpack(lo, hi, m2a[r]); myred[16 + r] = lo; myred[20 + r] = hi;
                f2unpack(lo, hi, m2b[r]); myred[24 + r] = lo; myred[28 + r] = hi;
            }
            myred[32] = sumr;
        }
        __syncthreads();
        for (int s = tid; s < 1056; s += 256) {
            float acc = 0.0f;
            #pragma unroll
            for (int ww = 0; ww < 8; ww++) acc += red[ww * 1056 + s];
            mom[s] = acc;
        }
        __syncthreads();

        // ================= stats =================
        if (tid < 32) {
            const float* mm = mom + tid * 33;
            float R = mm[32];
            float invR = 1.0f / R;
            float cs = 0.0f;
            #pragma unroll
            for (int d = 0; d < 16; d++) {
                float m  = mm[d] * invR;
                float sg = fmaf(-m, m, mm[16 + d] * invR);
                mu_s[tid * 17 + d] = m;
                cs += __logf(sg);
            }
            float cost = R * fmaf(16.0f, bv, cs);
            float act  = 1.0f / (1.0f + __expf(lam * (cost - ba)));
            if (it == 2) {
                float* on = out + (long)n * 19584 + xy;
                #pragma unroll
                for (int d = 0; d < 16; d++)
                    on[(tid * 16 + d) * 36] = mu_s[tid * 17 + d];
                on[(512 + tid) * 36] = act;
            } else {
                sfac_s[tid] = act * __expf(-0.5f * fmaf(16.0f, LOG2PI, cs));
            }
        }
        __syncthreads();
        if (it == 2) return;

        // ================= E phase =================
        {
            float sf = sfac_s[c];
            unsigned long long nmu0[4], nmu1[4];
            #pragma unroll
            for (int r = 0; r < 4; r++) {
                nmu0[r] = f2pack(-mu_s[c * 17 + r],     -mu_s[c * 17 + 4 + r]);
                nmu1[r] = f2pack(-mu_s[c * 17 + 8 + r], -mu_s[c * 17 + 12 + r]);
            }
            #pragma unroll 1
            for (int oo = 0; oo < 4; oo++) {
                int o = w * 4 + oo;
                #pragma unroll 3
                for (int ij = 0; ij < 9; ij++) {
                    int oij = o * 9 + ij;
                    const unsigned long long* pb = (const unsigned long long*)(pose2 + oij * 32);
                    const ulonglong2* wp = (const ulonglong2*)g_Wt + (oij * 4) * 32 + c;
                    unsigned long long v0[4], v1[4];
                    {
                        ulonglong2 wv = wp[0];
                        #pragma unroll
                        for (int r = 0; r < 4; r++) {
                            unsigned long long P = pb[r];
                            v0[r] = f2mul(wv.x, P); v1[r] = f2mul(wv.y, P);
                        }
                    }
                    #pragma unroll
                    for (int q = 1; q < 4; q++) {
                        ulonglong2 wv = wp[q * 32];
                        #pragma unroll
                        for (int r = 0; r < 4; r++) {
                            unsigned long long P = pb[q * 4 + r];
                            v0[r] = f2fma(wv.x, P, v0[r]); v1[r] = f2fma(wv.y, P, v1[r]);
                        }
                    }
                    unsigned long long ssd2;
                    {
                        unsigned long long dd = f2add(v0[0], nmu0[0]);
                        ssd2 = f2mul(dd, dd);
                    }
                    #pragma unroll
                    for (int r = 1; r < 4; r++) {
                        unsigned long long dd = f2add(v0[r], nmu0[r]);
                        ssd2 = f2fma(dd, dd, ssd2);
                    }
                    #pragma unroll
                    for (int r = 0; r < 4; r++) {
                        unsigned long long dd = f2add(v1[r], nmu1[r]);
                        ssd2 = f2fma(dd, dd, ssd2);
                    }
                    float slo, shi; f2unpack(slo, shi, ssd2);
                    float ph = sf * __expf(-(slo + shi));
                    // kperm=[0,2,1] self-inverse: these votes ARE votesE of the
                    // permuted slot -> file p_hat there (block-local smem).
                    int i2 = ij / 3, j2 = ij - i2 * 3;
                    int ip = (3 - i2) % 3, jp = (3 - j2) % 3;
                    ph_s[(o * 9 + ip * 3 + jp) * 33 + c] = ph;
                }
            }
        }
        __syncthreads();

        // ---- D pass: row sums -> global atomics ----
        float* Dg = (it == 0) ? g_D0 : g_D1;
        for (int row = tid; row < 288; row += 256) {
            const float* pr = ph_s + row * 33;
            float s = 0.0f;
            #pragma unroll
            for (int k = 0; k < 32; k++) s += pr[k];
            int o = row / 9, ij = row - o * 9;
            atomicAdd(&Dg[(n * 32 + o) * 169 + (2 * X + ij / 3) * 13 + (2 * Y + ij % 3)], s);
        }

        // ---- grid barrier ----
        __syncthreads();
        if (tid == 0) {
            __threadfence();
            atomicAdd(&g_bar[it], 1u);
            while (*((volatile unsigned*)&g_bar[it]) < 288u) { __nanosleep(32); }
        }
        __syncthreads();

        // ---- aD pass: a / D (L2 load; D never touched L1) ----
        for (int e = tid; e < 288; e += 256) {
            int o = e / 9, ij = e - o * 9;
            float Dv = __ldcg(&Dg[(n * 32 + o) * 169 + (2 * X + ij / 3) * 13 + (2 * Y + ij % 3)]);
            aD_s[e] = __fdividef(a_s[e], Dv);
        }
        __syncthreads();
    }
}

extern "C" void kernel_launch(void* const* d_in, const int* in_sizes, int n_in,
                              void* d_out, int out_size) {
    const float* x   = (const float*)d_in[0];
    const float* W   = (const float*)d_in[1];
    const float* bv  = (const float*)d_in[2];
    const float* ba  = (const float*)d_in[3];
    const float* lam = (const float*)d_in[4];
    float* out = (float*)d_out;

    const int smem = SMEM_FLOATS * 4;   // 83712 B
    cudaFuncSetAttribute(fused_kernel, cudaFuncAttributeMaxDynamicSharedMemorySize, smem);

    prep_kernel<<<576, 256>>>(W);
    fused_kernel<<<dim3(36, 8), 256, smem>>>(x, bv, ba, lam, out);
}